// round 13
// baseline (speedup 1.0000x reference)
#include <cuda_runtime.h>
#include <math.h>
#include <stdint.h>

#define BB 64      // batch
#define EE 256     // embed
#define SS 32      // seq
#define HH 16      // heads
#define HD 16      // head dim
#define PP 512     // pairs
#define KC 46      // classes
#define MROWS (BB*SS)   // 2048
#define NCOLS (3*EE)    // 768
#define NMT (MROWS/16)  // 128 m-tiles
#define NNT (NCOLS/8)   // 96 n-tiles
#define NKS (EE/8)      // 32 k-steps

// ---------------- scratch (device globals; no allocation allowed) ----------
__device__ __align__(16) float g_Afrag[NMT * NKS * 32 * 8];  // canned A frags (hi4,lo4)
__device__ __align__(16) float g_Bfrag[NNT * NKS * 32 * 4];  // canned B frags
__device__ __align__(16) float g_QKV[MROWS * NCOLS];
__device__ __align__(16) float g_O[BB * SS * EE];
__device__ __align__(16) float g_logprob[BB * KC];
__device__ int   g_i[PP], g_j[PP];
__device__ float g_valid[PP];
__device__ float g_cj[BB];
__device__ int   g_sel[PP];
__device__ unsigned g_hc;          // head-block completion counter (reset by setup)

__device__ __forceinline__ void split_tf32(float x, float& hi, float& lo) {
    uint32_t u;
    asm("cvt.rna.tf32.f32 %0, %1;" : "=r"(u) : "f"(x));
    hi = __uint_as_float(u);
    float r = x - hi;
    asm("cvt.rna.tf32.f32 %0, %1;" : "=r"(u) : "f"(r));
    lo = __uint_as_float(u);
}

__device__ __forceinline__ void mma_tf32(float c[4], float a0, float a1, float a2, float a3,
                                         float b0, float b1) {
    asm volatile(
        "mma.sync.aligned.m16n8k8.row.col.f32.tf32.tf32.f32 "
        "{%0,%1,%2,%3}, {%4,%5,%6,%7}, {%8,%9}, {%0,%1,%2,%3};"
        : "+f"(c[0]), "+f"(c[1]), "+f"(c[2]), "+f"(c[3])
        : "r"(__float_as_uint(a0)), "r"(__float_as_uint(a1)),
          "r"(__float_as_uint(a2)), "r"(__float_as_uint(a3)),
          "r"(__float_as_uint(b0)), "r"(__float_as_uint(b1)));
}

// ---------------- 1) fused setup: A-split | B-split(x2) | pair scan --------
// 113 blocks = one wave: 0..63 A-units, 64..111 two B-units each, 112 pairs.
__global__ void __launch_bounds__(256) setup_kernel(const float* __restrict__ feat,
                                                    const float* __restrict__ W,
                                                    const int* __restrict__ labels1) {
    int tid = threadIdx.x;
    int bx = blockIdx.x;
    if (bx < 64) {
        // ---- A split: A[m][k] = feat[b, k, s], m = b*32+s ----
        __shared__ float sA[256][33];
        int b = bx;
        int s = tid & 31, k0 = tid >> 5;
        for (int k = k0; k < 256; k += 8)
            sA[k][s] = feat[b * 8192 + k * 32 + s];
        __syncthreads();
        #pragma unroll
        for (int t = 0; t < 8; t++) {
            int idx = t * 256 + tid;
            int mt_l = idx >> 10;
            int rem = idx & 1023;
            int ks = rem >> 5, lane = rem & 31;
            int g = lane >> 2, tg = lane & 3;
            int r0 = mt_l * 16 + g;
            int k1 = ks * 8 + tg, k2 = k1 + 4;
            float a0 = sA[k1][r0], a1 = sA[k1][r0 + 8];
            float a2 = sA[k2][r0], a3 = sA[k2][r0 + 8];
            float h0, l0, h1, l1, h2, l2, h3, l3;
            split_tf32(a0, h0, l0); split_tf32(a1, h1, l1);
            split_tf32(a2, h2, l2); split_tf32(a3, h3, l3);
            int mt = b * 2 + mt_l;
            float4* dst = (float4*)&g_Afrag[((mt * NKS + ks) * 32 + lane) * 8];
            dst[0] = make_float4(h0, h1, h2, h3);
            dst[1] = make_float4(l0, l1, l2, l3);
        }
    } else if (bx < 112) {
        // ---- B split: 2 n-tiles per block ----
        __shared__ float sW[8][260];
        #pragma unroll
        for (int it = 0; it < 2; it++) {
            int nt = (bx - 64) * 2 + it;
            if (it) __syncthreads();
            int row = tid >> 5;
            int kk = (tid & 31) * 8;
            const float* wr = W + (nt * 8 + row) * 256 + kk;
            #pragma unroll
            for (int u = 0; u < 8; u++) sW[row][kk + u] = wr[u];
            __syncthreads();
            #pragma unroll
            for (int t = 0; t < 4; t++) {
                int idx = t * 256 + tid;
                int ks = idx >> 5, lane = idx & 31;
                int g = lane >> 2, tg = lane & 3;
                float b0 = sW[g][ks * 8 + tg], b1 = sW[g][ks * 8 + 4 + tg];
                float h0, l0, h1, l1;
                split_tf32(b0, h0, l0);
                split_tf32(b1, h1, l1);
                ((float4*)g_Bfrag)[(nt * NKS + ks) * 32 + lane] = make_float4(h0, h1, l0, l1);
            }
        }
    } else {
        // ---- pair setup ----
        __shared__ int l1[BB];
        __shared__ int cnt[256];
        __shared__ int off[257];
        __shared__ int cj[BB];
        if (tid == 0) g_hc = 0;          // reset completion counter every launch
        if (tid < BB) { l1[tid] = labels1[tid]; cj[tid] = 0; }
        __syncthreads();
        int base = tid * 16;
        int c = 0;
        #pragma unroll
        for (int u = 0; u < 16; u++) {
            int idx = base + u;
            c += (l1[idx >> 6] == l1[idx & 63]);
        }
        cnt[tid] = c;
        __syncthreads();
        if (tid == 0) {
            int acc = 0;
            for (int t = 0; t < 256; t++) { off[t] = acc; acc += cnt[t]; }
            off[256] = acc;
        }
        __syncthreads();
        int pos = off[tid];
        #pragma unroll
        for (int u = 0; u < 16; u++) {
            int idx = base + u;
            if (l1[idx >> 6] == l1[idx & 63]) {
                if (pos < PP) g_sel[pos] = idx;
                pos++;
            }
        }
        int total = off[256];
        for (int p2 = total + tid; p2 < PP; p2 += 256) g_sel[p2] = 0;
        __syncthreads();
        int nv = total < PP ? total : PP;
        for (int p = tid; p < PP; p += 256) {
            int s0 = g_sel[p];
            int i = s0 >> 6, j = s0 & 63;
            g_i[p] = i; g_j[p] = j;
            g_valid[p] = (p < nv) ? 1.0f : 0.0f;
            atomicAdd(&cj[j], 1);
        }
        __syncthreads();
        if (tid < BB) g_cj[tid] = (float)cj[tid];
    }
}

// ---------------- 2) QKV GEMM: one-wave fragment-direct tf32x3 -------------
// 128 blocks (16x8), block tile 128(M) x 96(N); warp tile 32x48; no smem.
__global__ void __launch_bounds__(256, 1) qkv_mma(const float* __restrict__ bias) {
    int bx = blockIdx.x;   // 0..15 (M)
    int by = blockIdx.y;   // 0..7  (N)
    int tid = threadIdx.x, warp = tid >> 5, lane = tid & 31;
    int g = lane >> 2, tg = lane & 3;
    int wr = warp >> 1, wc = warp & 1;
    int mtb = bx * 8 + wr * 2;     // 2 m-tiles per warp
    int ntb = by * 12 + wc * 6;    // 6 n-tiles per warp
    float c[2][6][4] = {};
    const float4* Af = (const float4*)g_Afrag;
    const float4* Bf = (const float4*)g_Bfrag;
    #pragma unroll 2
    for (int ks = 0; ks < NKS; ks++) {
        float4 ah[2], al[2], bf[6];
        #pragma unroll
        for (int mi = 0; mi < 2; mi++) {
            int ia = (((mtb + mi) * NKS + ks) * 32 + lane) * 2;
            ah[mi] = Af[ia];
            al[mi] = Af[ia + 1];
        }
        #pragma unroll
        for (int ni = 0; ni < 6; ni++)
            bf[ni] = Bf[((ntb + ni) * NKS + ks) * 32 + lane];
        #pragma unroll
        for (int mi = 0; mi < 2; mi++)
            #pragma unroll
            for (int ni = 0; ni < 6; ni++) {
                mma_tf32(c[mi][ni], ah[mi].x, ah[mi].y, ah[mi].z, ah[mi].w, bf[ni].x, bf[ni].y);
                mma_tf32(c[mi][ni], ah[mi].x, ah[mi].y, ah[mi].z, ah[mi].w, bf[ni].z, bf[ni].w);
                mma_tf32(c[mi][ni], al[mi].x, al[mi].y, al[mi].z, al[mi].w, bf[ni].x, bf[ni].y);
            }
    }
    #pragma unroll
    for (int mi = 0; mi < 2; mi++) {
        int m = bx * 128 + wr * 32 + mi * 16 + g;
        #pragma unroll
        for (int ni = 0; ni < 6; ni++) {
            int n = by * 96 + wc * 48 + ni * 8 + 2 * tg;
            float b0 = bias[n], b1 = bias[n + 1];
            *(float2*)(g_QKV + m * NCOLS + n) = make_float2(c[mi][ni][0] + b0, c[mi][ni][1] + b1);
            *(float2*)(g_QKV + (m + 8) * NCOLS + n) = make_float2(c[mi][ni][2] + b0, c[mi][ni][3] + b1);
        }
    }
}

// ---------------- 3) attention per (s,h): 4-way j-split, 1-pass softmax ----
// 256 threads: quarter q handles j in [q*16, q*16+16); fixed-order smem tree
// combine (quarters 1-3 write partials, quarter 0 sums + stores).
__global__ void __launch_bounds__(256) attn_kernel() {
    int s = blockIdx.x & 31;
    int h = blockIdx.x >> 5;
    __shared__ float Ks[BB][HD];
    __shared__ float Vs[BB][HD];
    __shared__ float cjs[BB];
    __shared__ float Pd[3][BB];
    __shared__ float Pa[3][BB][HD + 1];   // pad 17: conflict-free
    int tid = threadIdx.x;
    int q = tid >> 6;      // 0..3
    int b = tid & 63;

    const float* qkv_row = g_QKV + (b * SS + s) * NCOLS + h * HD;
    if (q == 0) {          // K rows
        const float4* kp = (const float4*)(qkv_row + EE);
        float4* kd = (float4*)Ks[b];
        kd[0] = kp[0]; kd[1] = kp[1]; kd[2] = kp[2]; kd[3] = kp[3];
    } else if (q == 1) {   // V rows
        const float4* vp = (const float4*)(qkv_row + 2 * EE);
        float4* vd = (float4*)Vs[b];
        vd[0] = vp[0]; vd[1] = vp[1]; vd[2] = vp[2]; vd[3] = vp[3];
    } else if (q == 2) {
        cjs[b] = g_cj[b];
    }
    float4 q0 = ((const float4*)qkv_row)[0];   // redundant across quarters; L1-hit
    float4 q1 = ((const float4*)qkv_row)[1];
    float4 q2 = ((const float4*)qkv_row)[2];
    float4 q3 = ((const float4*)qkv_row)[3];
    __syncthreads();

    float denom = 0.0f;
    float acc[HD];
    #pragma unroll
    for (int d = 0; d < HD; d++) acc[d] = 0.0f;
    int j0 = q << 4;
    #pragma unroll 4
    for (int jj = 0; jj < 16; jj++) {
        int j = j0 + jj;
        const float4* kr = (const float4*)Ks[j];
        float4 k0 = kr[0], k1 = kr[1], k2 = kr[2], k3 = kr[3];
        float p0 = q0.x * k0.x + q0.y * k0.y + q0.z * k0.z + q0.w * k0.w;
        float p1 = q1.x * k1.x + q1.y * k1.y + q1.z * k1.z + q1.w * k1.w;
        float p2 = q2.x * k2.x + q2.y * k2.y + q2.z * k2.z + q2.w * k2.w;
        float p3 = q3.x * k3.x + q3.y * k3.y + q3.z * k3.z + q3.w * k3.w;
        float sc = ((p0 + p1) + (p2 + p3)) * 0.25f;
        float p = cjs[j] * __expf(sc);     // scores O(1): no max pass (validated R7+)
        denom += p;
        const float4* vr = (const float4*)Vs[j];
        float4 v0 = vr[0], v1 = vr[1], v2 = vr[2], v3 = vr[3];
        acc[0] += p * v0.x;  acc[1] += p * v0.y;  acc[2] += p * v0.z;  acc[3] += p * v0.w;
        acc[4] += p * v1.x;  acc[5] += p * v1.y;  acc[6] += p * v1.z;  acc[7] += p * v1.w;
        acc[8] += p * v2.x;  acc[9] += p * v2.y;  acc[10] += p * v2.z; acc[11] += p * v2.w;
        acc[12] += p * v3.x; acc[13] += p * v3.y; acc[14] += p * v3.z; acc[15] += p * v3.w;
    }
    if (q) {
        Pd[q - 1][b] = denom;
        #pragma unroll
        for (int d = 0; d < HD; d++) Pa[q - 1][b][d] = acc[d];
    }
    __syncthreads();
    if (q == 0) {
        denom += Pd[0][b] + Pd[1][b] + Pd[2][b];
        float inv = 1.0f / denom;
        float* op = g_O + (b * SS + s) * EE + h * HD;
        #pragma unroll
        for (int d = 0; d < HD; d++)
            op[d] = (acc[d] + Pa[0][b][d] + Pa[1][b][d] + Pa[2][b][d]) * inv;
    }
}

// ---------------- 4) head: 512 threads, k-split dots + (last block) loss ---
__global__ void __launch_bounds__(512) head_kernel(const float* __restrict__ Wo,
                                                   const float* __restrict__ bo,
                                                   const float* __restrict__ fw,
                                                   const float* __restrict__ fb,
                                                   const float* __restrict__ Hw,
                                                   const float* __restrict__ hb,
                                                   const int* __restrict__ labels0,
                                                   float* __restrict__ out) {
    int b = blockIdx.x;
    __shared__ float Gs[EE];
    __shared__ float Gp[EE];     // half-1 partials
    __shared__ float hs[EE];
    __shared__ float hp[EE];
    __shared__ float ls[64];
    __shared__ float lp[64];
    __shared__ float fws[SS];
    __shared__ float sfw_sh;
    __shared__ unsigned last_sh;
    int tid = threadIdx.x;
    int half = tid >> 8;           // 0/1 : k-range split
    int t = tid & 255;
    if (tid < SS) fws[tid] = fw[tid];
    __syncthreads();
    if (tid < 32) {
        float v = fws[tid];
        #pragma unroll
        for (int o = 16; o > 0; o >>= 1) v += __shfl_xor_sync(0xffffffffu, v, o);
        if (tid == 0) sfw_sh = v;
    }
    {   // G[e] — s-range split across halves, fixed-order combine
        const float* ob = g_O + b * SS * EE + t;
        int s0 = half * 16;
        float a0 = 0.0f, a1 = 0.0f;
        #pragma unroll
        for (int s = 0; s < 16; s += 2) {
            a0 += ob[(s0 + s) * EE] * fws[s0 + s];
            a1 += ob[(s0 + s + 1) * EE] * fws[s0 + s + 1];
        }
        if (half) Gp[t] = a0 + a1;
        __syncthreads();
        if (!half) Gs[t] = (a0 + a1) + Gp[t];
    }
    __syncthreads();
    {   // h[r] = dot(G, Wo[r]) — k-split (128 each), 2 accumulators
        int r = t;
        const float4* wrow = (const float4*)(Wo + r * EE) + half * 32;
        const float4* gv4 = (const float4*)Gs + half * 32;
        float pa = 0.0f, pb = 0.0f;
        #pragma unroll 8
        for (int k = 0; k < 32; k += 2) {
            float4 wv = wrow[k];
            float4 gv = gv4[k];
            pa += wv.x * gv.x + wv.y * gv.y + wv.z * gv.z + wv.w * gv.w;
            float4 wv2 = wrow[k + 1];
            float4 gv2 = gv4[k + 1];
            pb += wv2.x * gv2.x + wv2.y * gv2.y + wv2.z * gv2.z + wv2.w * gv2.w;
        }
        if (half) hp[r] = pa + pb;
        __syncthreads();
        if (!half) hs[r] = (pa + pb) + hp[r] + sfw_sh * bo[r] + fb[0];
    }
    __syncthreads();
    if (t < KC) {   // logits — k-split
        const float4* wrow = (const float4*)(Hw + t * EE) + half * 32;
        const float4* hv4 = (const float4*)hs + half * 32;
        float pa = 0.0f, pb = 0.0f;
        #pragma unroll 8
        for (int k = 0; k < 32; k += 2) {
            float4 wv = wrow[k];
            float4 hv = hv4[k];
            pa += wv.x * hv.x + wv.y * hv.y + wv.z * hv.z + wv.w * hv.w;
            float4 wv2 = wrow[k + 1];
            float4 hv2 = hv4[k + 1];
            pb += wv2.x * hv2.x + wv2.y * hv2.y + wv2.z * hv2.z + wv2.w * hv2.w;
        }
        if (half) lp[t] = pa + pb;
    }
    __syncthreads();
    if (!half && t < KC) ls[t] = /* own half */ 0.0f;  // placeholder overwritten below
    // NOTE: combine must read lp after sync; do it here (no extra sync needed)
    if (!half && t < KC) {
        const float4* wrow = (const float4*)(Hw + t * EE);
        const float4* hv4 = (const float4*)hs;
        float pa = 0.0f, pb = 0.0f;
        #pragma unroll 8
        for (int k = 0; k < 32; k += 2) {
            float4 wv = wrow[k];
            float4 hv = hv4[k];
            pa += wv.x * hv.x + wv.y * hv.y + wv.z * hv.z + wv.w * hv.w;
            float4 wv2 = wrow[k + 1];
            float4 hv2 = hv4[k + 1];
            pb += wv2.x * hv2.x + wv2.y * hv2.y + wv2.z * hv2.z + wv2.w * hv2.w;
        }
        ls[t] = (pa + pb) + lp[t] + hb[t];
    }
    __syncthreads();
    if (tid < 32) {
        int lane = tid;
        float v1 = (lane < KC) ? ls[lane] : -1e30f;
        float v2 = (lane + 32 < KC) ? ls[lane + 32] : -1e30f;
        float mx = fmaxf(v1, v2);
        #pragma unroll
        for (int o = 16; o > 0; o >>= 1) mx = fmaxf(mx, __shfl_xor_sync(0xffffffffu, mx, o));
        float se = ((lane < KC) ? __expf(v1 - mx) : 0.0f)
                 + ((lane + 32 < KC) ? __expf(v2 - mx) : 0.0f);
        #pragma unroll
        for (int o = 16; o > 0; o >>= 1) se += __shfl_xor_sync(0xffffffffu, se, o);
        float lse = mx + logf(se);
        if (lane < KC) g_logprob[b * KC + lane] = v1 - lse;
        if (lane + 32 < KC) g_logprob[b * KC + lane + 32] = v2 - lse;
    }
    // ---- last-block loss: deterministic, runs once all 64 blocks wrote ----
    __threadfence();
    __syncthreads();
    if (tid == 0) last_sh = (atomicAdd(&g_hc, 1u) == (unsigned)(BB - 1));
    __syncthreads();
    if (!last_sh) return;
    __threadfence();

    __shared__ int counts[KC];
    __shared__ float rn[16], rd[16];
    if (tid < KC) counts[tid] = 0;
    __syncthreads();
    // one pair per thread (512 threads = PP)
    int i = g_i[tid], j = g_j[tid];
    float valid = g_valid[tid];
    int a = labels0[i], c = labels0[j];
    int y;
    if (a == c) y = 0;
    else {
        int lo = min(a, c), hi = max(a, c);
        y = 1 + lo * 9 - (lo * (lo - 1)) / 2 + (hi - lo - 1);
    }
    if (valid > 0.0f) atomicAdd(&counts[y], 1);
    __syncthreads();
    float cw = counts[y] > 0 ? 1.0f / (float)counts[y] : 0.0f;
    float wy = cw * valid;
    float num = wy * (-g_logprob[i * KC + y]);
    float den = wy;
    int lane3 = tid & 31, w3 = tid >> 5;
    #pragma unroll
    for (int o = 16; o > 0; o >>= 1) {
        num += __shfl_down_sync(0xffffffffu, num, o);
        den += __shfl_down_sync(0xffffffffu, den, o);
    }
    if (lane3 == 0) { rn[w3] = num; rd[w3] = den; }
    __syncthreads();
    if (tid == 0) {
        float n2 = 0.0f, d2 = 0.0f;
        #pragma unroll
        for (int t2 = 0; t2 < 16; t2++) { n2 += rn[t2]; d2 += rd[t2]; }
        out[0] = n2 / d2;
    }
}

// ---------------------------------------------------------------------------
extern "C" void kernel_launch(void* const* d_in, const int* in_sizes, int n_in,
                              void* d_out, int out_size) {
    const float* feat    = (const float*)d_in[0];
    const int*   labels0 = (const int*)d_in[1];
    const int*   labels1 = (const int*)d_in[2];
    const float* ipw     = (const float*)d_in[3];
    const float* ipb     = (const float*)d_in[4];
    const float* opw     = (const float*)d_in[5];
    const float* opb     = (const float*)d_in[6];
    const float* fw      = (const float*)d_in[7];
    const float* fbv     = (const float*)d_in[8];
    const float* hw      = (const float*)d_in[9];
    const float* hbv     = (const float*)d_in[10];
    float* out = (float*)d_out;

    setup_kernel<<<113, 256>>>(feat, ipw, labels1);   // one wave
    dim3 g(16, 8);                            // one wave: 128 blocks
    qkv_mma<<<g, 256>>>(ipb);
    attn_kernel<<<SS * HH, 256>>>();          // 512 blocks, 4-way split-j
    head_kernel<<<BB, 512>>>(opw, opb, fw, fbv, hw, hbv, labels0, out);
}

// round 16
// speedup vs baseline: 1.0835x; 1.0835x over previous
#include <cuda_runtime.h>
#include <math.h>
#include <stdint.h>

#define BB 64      // batch
#define EE 256     // embed
#define SS 32      // seq
#define HH 16      // heads
#define HD 16      // head dim
#define PP 512     // pairs
#define KC 46      // classes
#define MROWS (BB*SS)   // 2048
#define NCOLS (3*EE)    // 768
#define NMT (MROWS/16)  // 128 m-tiles
#define NNT (NCOLS/8)   // 96 n-tiles
#define NKS (EE/8)      // 32 k-steps

// ---------------- scratch (device globals; no allocation allowed) ----------
__device__ __align__(16) float g_Afrag[NMT * NKS * 32 * 8];  // canned A frags (hi4,lo4)
__device__ __align__(16) float g_Bfrag[NNT * NKS * 32 * 4];  // canned B frags
__device__ __align__(16) float g_QKV[MROWS * NCOLS];
__device__ __align__(16) float g_O[BB * SS * EE];
__device__ __align__(16) float g_logprob[BB * KC];
__device__ int   g_i[PP], g_j[PP];
__device__ float g_valid[PP];
__device__ float g_cj[BB];
__device__ int   g_sel[PP];
__device__ unsigned g_hc;          // head-block completion counter (reset by setup)

__device__ __forceinline__ void split_tf32(float x, float& hi, float& lo) {
    uint32_t u;
    asm("cvt.rna.tf32.f32 %0, %1;" : "=r"(u) : "f"(x));
    hi = __uint_as_float(u);
    float r = x - hi;
    asm("cvt.rna.tf32.f32 %0, %1;" : "=r"(u) : "f"(r));
    lo = __uint_as_float(u);
}

__device__ __forceinline__ void mma_tf32(float c[4], float a0, float a1, float a2, float a3,
                                         float b0, float b1) {
    asm volatile(
        "mma.sync.aligned.m16n8k8.row.col.f32.tf32.tf32.f32 "
        "{%0,%1,%2,%3}, {%4,%5,%6,%7}, {%8,%9}, {%0,%1,%2,%3};"
        : "+f"(c[0]), "+f"(c[1]), "+f"(c[2]), "+f"(c[3])
        : "r"(__float_as_uint(a0)), "r"(__float_as_uint(a1)),
          "r"(__float_as_uint(a2)), "r"(__float_as_uint(a3)),
          "r"(__float_as_uint(b0)), "r"(__float_as_uint(b1)));
}

// ---------------- 1) fused setup: A-split | B-split(x2) | pair scan --------
// 113 blocks = one wave: 0..63 A-units, 64..111 two B-units each, 112 pairs.
__global__ void __launch_bounds__(256) setup_kernel(const float* __restrict__ feat,
                                                    const float* __restrict__ W,
                                                    const int* __restrict__ labels1) {
    int tid = threadIdx.x;
    int bx = blockIdx.x;
    if (bx < 64) {
        // ---- A split: A[m][k] = feat[b, k, s], m = b*32+s ----
        __shared__ float sA[256][33];
        int b = bx;
        int s = tid & 31, k0 = tid >> 5;
        for (int k = k0; k < 256; k += 8)
            sA[k][s] = feat[b * 8192 + k * 32 + s];
        __syncthreads();
        #pragma unroll
        for (int t = 0; t < 8; t++) {
            int idx = t * 256 + tid;
            int mt_l = idx >> 10;
            int rem = idx & 1023;
            int ks = rem >> 5, lane = rem & 31;
            int g = lane >> 2, tg = lane & 3;
            int r0 = mt_l * 16 + g;
            int k1 = ks * 8 + tg, k2 = k1 + 4;
            float a0 = sA[k1][r0], a1 = sA[k1][r0 + 8];
            float a2 = sA[k2][r0], a3 = sA[k2][r0 + 8];
            float h0, l0, h1, l1, h2, l2, h3, l3;
            split_tf32(a0, h0, l0); split_tf32(a1, h1, l1);
            split_tf32(a2, h2, l2); split_tf32(a3, h3, l3);
            int mt = b * 2 + mt_l;
            float4* dst = (float4*)&g_Afrag[((mt * NKS + ks) * 32 + lane) * 8];
            dst[0] = make_float4(h0, h1, h2, h3);
            dst[1] = make_float4(l0, l1, l2, l3);
        }
    } else if (bx < 112) {
        // ---- B split: 2 n-tiles per block ----
        __shared__ float sW[8][260];
        #pragma unroll
        for (int it = 0; it < 2; it++) {
            int nt = (bx - 64) * 2 + it;
            if (it) __syncthreads();
            int row = tid >> 5;
            int kk = (tid & 31) * 8;
            const float* wr = W + (nt * 8 + row) * 256 + kk;
            #pragma unroll
            for (int u = 0; u < 8; u++) sW[row][kk + u] = wr[u];
            __syncthreads();
            #pragma unroll
            for (int t = 0; t < 4; t++) {
                int idx = t * 256 + tid;
                int ks = idx >> 5, lane = idx & 31;
                int g = lane >> 2, tg = lane & 3;
                float b0 = sW[g][ks * 8 + tg], b1 = sW[g][ks * 8 + 4 + tg];
                float h0, l0, h1, l1;
                split_tf32(b0, h0, l0);
                split_tf32(b1, h1, l1);
                ((float4*)g_Bfrag)[(nt * NKS + ks) * 32 + lane] = make_float4(h0, h1, l0, l1);
            }
        }
    } else {
        // ---- pair setup ----
        __shared__ int l1[BB];
        __shared__ int cnt[256];
        __shared__ int off[257];
        __shared__ int cj[BB];
        if (tid == 0) g_hc = 0;          // reset completion counter every launch
        if (tid < BB) { l1[tid] = labels1[tid]; cj[tid] = 0; }
        __syncthreads();
        int base = tid * 16;
        int c = 0;
        #pragma unroll
        for (int u = 0; u < 16; u++) {
            int idx = base + u;
            c += (l1[idx >> 6] == l1[idx & 63]);
        }
        cnt[tid] = c;
        __syncthreads();
        if (tid == 0) {
            int acc = 0;
            for (int t = 0; t < 256; t++) { off[t] = acc; acc += cnt[t]; }
            off[256] = acc;
        }
        __syncthreads();
        int pos = off[tid];
        #pragma unroll
        for (int u = 0; u < 16; u++) {
            int idx = base + u;
            if (l1[idx >> 6] == l1[idx & 63]) {
                if (pos < PP) g_sel[pos] = idx;
                pos++;
            }
        }
        int total = off[256];
        for (int p2 = total + tid; p2 < PP; p2 += 256) g_sel[p2] = 0;
        __syncthreads();
        int nv = total < PP ? total : PP;
        for (int p = tid; p < PP; p += 256) {
            int s0 = g_sel[p];
            int i = s0 >> 6, j = s0 & 63;
            g_i[p] = i; g_j[p] = j;
            g_valid[p] = (p < nv) ? 1.0f : 0.0f;
            atomicAdd(&cj[j], 1);
        }
        __syncthreads();
        if (tid < BB) g_cj[tid] = (float)cj[tid];
    }
}

// ---------------- 2) QKV GEMM: one-wave fragment-direct tf32x3 -------------
// 128 blocks (16x8), block tile 128(M) x 96(N); warp tile 32x48; no smem.
__global__ void __launch_bounds__(256, 1) qkv_mma(const float* __restrict__ bias) {
    int bx = blockIdx.x;   // 0..15 (M)
    int by = blockIdx.y;   // 0..7  (N)
    int tid = threadIdx.x, warp = tid >> 5, lane = tid & 31;
    int g = lane >> 2, tg = lane & 3;
    int wr = warp >> 1, wc = warp & 1;
    int mtb = bx * 8 + wr * 2;     // 2 m-tiles per warp
    int ntb = by * 12 + wc * 6;    // 6 n-tiles per warp
    float c[2][6][4] = {};
    const float4* Af = (const float4*)g_Afrag;
    const float4* Bf = (const float4*)g_Bfrag;
    #pragma unroll 2
    for (int ks = 0; ks < NKS; ks++) {
        float4 ah[2], al[2], bf[6];
        #pragma unroll
        for (int mi = 0; mi < 2; mi++) {
            int ia = (((mtb + mi) * NKS + ks) * 32 + lane) * 2;
            ah[mi] = Af[ia];
            al[mi] = Af[ia + 1];
        }
        #pragma unroll
        for (int ni = 0; ni < 6; ni++)
            bf[ni] = Bf[((ntb + ni) * NKS + ks) * 32 + lane];
        #pragma unroll
        for (int mi = 0; mi < 2; mi++)
            #pragma unroll
            for (int ni = 0; ni < 6; ni++) {
                mma_tf32(c[mi][ni], ah[mi].x, ah[mi].y, ah[mi].z, ah[mi].w, bf[ni].x, bf[ni].y);
                mma_tf32(c[mi][ni], ah[mi].x, ah[mi].y, ah[mi].z, ah[mi].w, bf[ni].z, bf[ni].w);
                mma_tf32(c[mi][ni], al[mi].x, al[mi].y, al[mi].z, al[mi].w, bf[ni].x, bf[ni].y);
            }
    }
    #pragma unroll
    for (int mi = 0; mi < 2; mi++) {
        int m = bx * 128 + wr * 32 + mi * 16 + g;
        #pragma unroll
        for (int ni = 0; ni < 6; ni++) {
            int n = by * 96 + wc * 48 + ni * 8 + 2 * tg;
            float b0 = bias[n], b1 = bias[n + 1];
            *(float2*)(g_QKV + m * NCOLS + n) = make_float2(c[mi][ni][0] + b0, c[mi][ni][1] + b1);
            *(float2*)(g_QKV + (m + 8) * NCOLS + n) = make_float2(c[mi][ni][2] + b0, c[mi][ni][3] + b1);
        }
    }
}

// ---------------- 3) attention per (s,h): split-j, 1-pass softmax ----------
// (R12-proven form) 128 threads: half 0 does j in [0,32), half 1 j in [32,64).
__global__ void __launch_bounds__(128) attn_kernel() {
    int s = blockIdx.x & 31;
    int h = blockIdx.x >> 5;
    __shared__ float Ks[BB][HD];
    __shared__ float Vs[BB][HD];
    __shared__ float cjs[BB];
    __shared__ float Pd[BB];            // upper-half partial denom
    __shared__ float Pa[BB][HD + 1];    // upper-half partial acc (17: conflict-free)
    int tid = threadIdx.x;
    int half = tid >> 6;
    int b = tid & 63;

    const float* qkv_row = g_QKV + (b * SS + s) * NCOLS + h * HD;
    if (half == 0) {    // K rows + counts
        const float4* kp = (const float4*)(qkv_row + EE);
        float4* kd = (float4*)Ks[b];
        kd[0] = kp[0]; kd[1] = kp[1]; kd[2] = kp[2]; kd[3] = kp[3];
        cjs[b] = g_cj[b];
    } else {            // V rows
        const float4* vp = (const float4*)(qkv_row + 2 * EE);
        float4* vd = (float4*)Vs[b];
        vd[0] = vp[0]; vd[1] = vp[1]; vd[2] = vp[2]; vd[3] = vp[3];
    }
    float4 q0 = ((const float4*)qkv_row)[0];
    float4 q1 = ((const float4*)qkv_row)[1];
    float4 q2 = ((const float4*)qkv_row)[2];
    float4 q3 = ((const float4*)qkv_row)[3];
    __syncthreads();

    float denom = 0.0f;
    float acc[HD];
    #pragma unroll
    for (int d = 0; d < HD; d++) acc[d] = 0.0f;
    int j0 = half << 5;
    #pragma unroll 4
    for (int jj = 0; jj < 32; jj++) {
        int j = j0 + jj;
        const float4* kr = (const float4*)Ks[j];
        float4 k0 = kr[0], k1 = kr[1], k2 = kr[2], k3 = kr[3];
        float p0 = q0.x * k0.x + q0.y * k0.y + q0.z * k0.z + q0.w * k0.w;
        float p1 = q1.x * k1.x + q1.y * k1.y + q1.z * k1.z + q1.w * k1.w;
        float p2 = q2.x * k2.x + q2.y * k2.y + q2.z * k2.z + q2.w * k2.w;
        float p3 = q3.x * k3.x + q3.y * k3.y + q3.z * k3.z + q3.w * k3.w;
        float sc = ((p0 + p1) + (p2 + p3)) * 0.25f;
        float p = cjs[j] * __expf(sc);     // scores O(1): no max pass (validated R7+)
        denom += p;
        const float4* vr = (const float4*)Vs[j];
        float4 v0 = vr[0], v1 = vr[1], v2 = vr[2], v3 = vr[3];
        acc[0] += p * v0.x;  acc[1] += p * v0.y;  acc[2] += p * v0.z;  acc[3] += p * v0.w;
        acc[4] += p * v1.x;  acc[5] += p * v1.y;  acc[6] += p * v1.z;  acc[7] += p * v1.w;
        acc[8] += p * v2.x;  acc[9] += p * v2.y;  acc[10] += p * v2.z; acc[11] += p * v2.w;
        acc[12] += p * v3.x; acc[13] += p * v3.y; acc[14] += p * v3.z; acc[15] += p * v3.w;
    }
    if (half) {
        Pd[b] = denom;
        #pragma unroll
        for (int d = 0; d < HD; d++) Pa[b][d] = acc[d];
    }
    __syncthreads();
    if (!half) {
        denom += Pd[b];
        float inv = 1.0f / denom;
        float* op = g_O + (b * SS + s) * EE + h * HD;
        #pragma unroll
        for (int d = 0; d < HD; d++) op[d] = (acc[d] + Pa[b][d]) * inv;
    }
}

// ---------------- 4) head: 512 threads, k-split dots + (last block) loss ---
__global__ void __launch_bounds__(512) head_kernel(const float* __restrict__ Wo,
                                                   const float* __restrict__ bo,
                                                   const float* __restrict__ fw,
                                                   const float* __restrict__ fb,
                                                   const float* __restrict__ Hw,
                                                   const float* __restrict__ hb,
                                                   const int* __restrict__ labels0,
                                                   float* __restrict__ out) {
    int b = blockIdx.x;
    __shared__ float Gs[EE];
    __shared__ float Gp[EE];     // half-1 partials
    __shared__ float hs[EE];
    __shared__ float hp[EE];
    __shared__ float ls[64];
    __shared__ float lp[64];
    __shared__ float fws[SS];
    __shared__ float sfw_sh;
    __shared__ unsigned last_sh;
    int tid = threadIdx.x;
    int half = tid >> 8;           // 0/1 : k-range split
    int t = tid & 255;
    if (tid < SS) fws[tid] = fw[tid];
    __syncthreads();
    if (tid < 32) {
        float v = fws[tid];
        #pragma unroll
        for (int o = 16; o > 0; o >>= 1) v += __shfl_xor_sync(0xffffffffu, v, o);
        if (tid == 0) sfw_sh = v;
    }
    {   // G[e] — s-range split across halves, fixed-order combine
        const float* ob = g_O + b * SS * EE + t;
        int s0 = half * 16;
        float a0 = 0.0f, a1 = 0.0f;
        #pragma unroll
        for (int s = 0; s < 16; s += 2) {
            a0 += ob[(s0 + s) * EE] * fws[s0 + s];
            a1 += ob[(s0 + s + 1) * EE] * fws[s0 + s + 1];
        }
        if (half) Gp[t] = a0 + a1;
        __syncthreads();
        if (!half) Gs[t] = (a0 + a1) + Gp[t];
    }
    __syncthreads();
    {   // h[r] = dot(G, Wo[r]) — k-split (128 each), 2 accumulators
        int r = t;
        const float4* wrow = (const float4*)(Wo + r * EE) + half * 32;
        const float4* gv4 = (const float4*)Gs + half * 32;
        float pa = 0.0f, pb = 0.0f;
        #pragma unroll 8
        for (int k = 0; k < 32; k += 2) {
            float4 wv = wrow[k];
            float4 gv = gv4[k];
            pa += wv.x * gv.x + wv.y * gv.y + wv.z * gv.z + wv.w * gv.w;
            float4 wv2 = wrow[k + 1];
            float4 gv2 = gv4[k + 1];
            pb += wv2.x * gv2.x + wv2.y * gv2.y + wv2.z * gv2.z + wv2.w * gv2.w;
        }
        if (half) hp[r] = pa + pb;
        __syncthreads();
        if (!half) hs[r] = (pa + pb) + hp[r] + sfw_sh * bo[r] + fb[0];
    }
    __syncthreads();
    {   // logits — k-split, store-and-combine (no recompute)
        float lpart = 0.0f;
        if (t < KC) {
            const float4* wrow = (const float4*)(Hw + t * EE) + half * 32;
            const float4* hv4 = (const float4*)hs + half * 32;
            float pa = 0.0f, pb = 0.0f;
            #pragma unroll 8
            for (int k = 0; k < 32; k += 2) {
                float4 wv = wrow[k];
                float4 hv = hv4[k];
                pa += wv.x * hv.x + wv.y * hv.y + wv.z * hv.z + wv.w * hv.w;
                float4 wv2 = wrow[k + 1];
                float4 hv2 = hv4[k + 1];
                pb += wv2.x * hv2.x + wv2.y * hv2.y + wv2.z * hv2.z + wv2.w * hv2.w;
            }
            lpart = pa + pb;
            if (half) lp[t] = lpart;
        }
        __syncthreads();
        if (!half && t < KC) ls[t] = lpart + lp[t] + hb[t];
    }
    __syncthreads();
    if (tid < 32) {
        int lane = tid;
        float v1 = (lane < KC) ? ls[lane] : -1e30f;
        float v2 = (lane + 32 < KC) ? ls[lane + 32] : -1e30f;
        float mx = fmaxf(v1, v2);
        #pragma unroll
        for (int o = 16; o > 0; o >>= 1) mx = fmaxf(mx, __shfl_xor_sync(0xffffffffu, mx, o));
        float se = ((lane < KC) ? __expf(v1 - mx) : 0.0f)
                 + ((lane + 32 < KC) ? __expf(v2 - mx) : 0.0f);
        #pragma unroll
        for (int o = 16; o > 0; o >>= 1) se += __shfl_xor_sync(0xffffffffu, se, o);
        float lse = mx + logf(se);
        if (lane < KC) g_logprob[b * KC + lane] = v1 - lse;
        if (lane + 32 < KC) g_logprob[b * KC + lane + 32] = v2 - lse;
    }
    // ---- last-block loss: deterministic, runs once all 64 blocks wrote ----
    __threadfence();
    __syncthreads();
    if (tid == 0) last_sh = (atomicAdd(&g_hc, 1u) == (unsigned)(BB - 1));
    __syncthreads();
    if (!last_sh) return;
    __threadfence();

    __shared__ int counts[KC];
    __shared__ float rn[16], rd[16];
    if (tid < KC) counts[tid] = 0;
    __syncthreads();
    // one pair per thread (512 threads = PP)
    int i = g_i[tid], j = g_j[tid];
    float valid = g_valid[tid];
    int a = labels0[i], c = labels0[j];
    int y;
    if (a == c) y = 0;
    else {
        int lo = min(a, c), hi = max(a, c);
        y = 1 + lo * 9 - (lo * (lo - 1)) / 2 + (hi - lo - 1);
    }
    if (valid > 0.0f) atomicAdd(&counts[y], 1);
    __syncthreads();
    float cw = counts[y] > 0 ? 1.0f / (float)counts[y] : 0.0f;
    float wy = cw * valid;
    float num = wy * (-g_logprob[i * KC + y]);
    float den = wy;
    int lane3 = tid & 31, w3 = tid >> 5;
    #pragma unroll
    for (int o = 16; o > 0; o >>= 1) {
        num += __shfl_down_sync(0xffffffffu, num, o);
        den += __shfl_down_sync(0xffffffffu, den, o);
    }
    if (lane3 == 0) { rn[w3] = num; rd[w3] = den; }
    __syncthreads();
    if (tid == 0) {
        float n2 = 0.0f, d2 = 0.0f;
        #pragma unroll
        for (int t2 = 0; t2 < 16; t2++) { n2 += rn[t2]; d2 += rd[t2]; }
        out[0] = n2 / d2;
    }
}

// ---------------------------------------------------------------------------
extern "C" void kernel_launch(void* const* d_in, const int* in_sizes, int n_in,
                              void* d_out, int out_size) {
    const float* feat    = (const float*)d_in[0];
    const int*   labels0 = (const int*)d_in[1];
    const int*   labels1 = (const int*)d_in[2];
    const float* ipw     = (const float*)d_in[3];
    const float* ipb     = (const float*)d_in[4];
    const float* opw     = (const float*)d_in[5];
    const float* opb     = (const float*)d_in[6];
    const float* fw      = (const float*)d_in[7];
    const float* fbv     = (const float*)d_in[8];
    const float* hw      = (const float*)d_in[9];
    const float* hbv     = (const float*)d_in[10];
    float* out = (float*)d_out;

    setup_kernel<<<113, 256>>>(feat, ipw, labels1);   // one wave
    dim3 g(16, 8);                            // one wave: 128 blocks
    qkv_mma<<<g, 256>>>(ipb);
    attn_kernel<<<SS * HH, 128>>>();          // 512 blocks, 2-way split-j (R12)
    head_kernel<<<BB, 512>>>(opw, opb, fw, fbv, hw, hbv, labels0, out);
}

// round 17
// speedup vs baseline: 1.1006x; 1.0157x over previous
#include <cuda_runtime.h>
#include <math.h>
#include <stdint.h>

#define BB 64      // batch
#define EE 256     // embed
#define SS 32      // seq
#define HH 16      // heads
#define HD 16      // head dim
#define PP 512     // pairs
#define KC 46      // classes
#define MROWS (BB*SS)   // 2048
#define NCOLS (3*EE)    // 768
#define NMT (MROWS/16)  // 128 m-tiles
#define NNT (NCOLS/8)   // 96 n-tiles
#define NKS (EE/8)      // 32 k-steps

// ---------------- scratch (device globals; no allocation allowed) ----------
__device__ __align__(16) float g_Afrag[NMT * NKS * 32 * 8];  // canned A frags (hi4,lo4)
__device__ __align__(16) float g_Bfrag[NNT * NKS * 32 * 4];  // canned B frags
__device__ __align__(16) float g_QKV[MROWS * NCOLS];
__device__ __align__(16) float g_O[BB * SS * EE];
__device__ __align__(16) float g_h[BB * EE];                 // post-Wo hidden, per b
__device__ __align__(16) float g_logprob[BB * KC];
__device__ int   g_i[PP], g_j[PP];
__device__ float g_valid[PP];
__device__ float g_cj[BB];
__device__ int   g_sel[PP];
__device__ unsigned g_hb[BB];      // per-b head-half completion (reset by setup)
__device__ unsigned g_hc;          // global head-block counter (reset by setup)

__device__ __forceinline__ void split_tf32(float x, float& hi, float& lo) {
    uint32_t u;
    asm("cvt.rna.tf32.f32 %0, %1;" : "=r"(u) : "f"(x));
    hi = __uint_as_float(u);
    float r = x - hi;
    asm("cvt.rna.tf32.f32 %0, %1;" : "=r"(u) : "f"(r));
    lo = __uint_as_float(u);
}

__device__ __forceinline__ void mma_tf32(float c[4], float a0, float a1, float a2, float a3,
                                         float b0, float b1) {
    asm volatile(
        "mma.sync.aligned.m16n8k8.row.col.f32.tf32.tf32.f32 "
        "{%0,%1,%2,%3}, {%4,%5,%6,%7}, {%8,%9}, {%0,%1,%2,%3};"
        : "+f"(c[0]), "+f"(c[1]), "+f"(c[2]), "+f"(c[3])
        : "r"(__float_as_uint(a0)), "r"(__float_as_uint(a1)),
          "r"(__float_as_uint(a2)), "r"(__float_as_uint(a3)),
          "r"(__float_as_uint(b0)), "r"(__float_as_uint(b1)));
}

// ---------------- 1) fused setup: A-split | B-split(x2) | pair scan --------
// 113 blocks = one wave: 0..63 A-units, 64..111 two B-units each, 112 pairs.
__global__ void __launch_bounds__(256) setup_kernel(const float* __restrict__ feat,
                                                    const float* __restrict__ W,
                                                    const int* __restrict__ labels1) {
    int tid = threadIdx.x;
    int bx = blockIdx.x;
    if (bx < 64) {
        // ---- A split: A[m][k] = feat[b, k, s], m = b*32+s ----
        __shared__ float sA[256][33];
        int b = bx;
        int s = tid & 31, k0 = tid >> 5;
        for (int k = k0; k < 256; k += 8)
            sA[k][s] = feat[b * 8192 + k * 32 + s];
        __syncthreads();
        #pragma unroll
        for (int t = 0; t < 8; t++) {
            int idx = t * 256 + tid;
            int mt_l = idx >> 10;
            int rem = idx & 1023;
            int ks = rem >> 5, lane = rem & 31;
            int g = lane >> 2, tg = lane & 3;
            int r0 = mt_l * 16 + g;
            int k1 = ks * 8 + tg, k2 = k1 + 4;
            float a0 = sA[k1][r0], a1 = sA[k1][r0 + 8];
            float a2 = sA[k2][r0], a3 = sA[k2][r0 + 8];
            float h0, l0, h1, l1, h2, l2, h3, l3;
            split_tf32(a0, h0, l0); split_tf32(a1, h1, l1);
            split_tf32(a2, h2, l2); split_tf32(a3, h3, l3);
            int mt = b * 2 + mt_l;
            float4* dst = (float4*)&g_Afrag[((mt * NKS + ks) * 32 + lane) * 8];
            dst[0] = make_float4(h0, h1, h2, h3);
            dst[1] = make_float4(l0, l1, l2, l3);
        }
    } else if (bx < 112) {
        // ---- B split: 2 n-tiles per block ----
        __shared__ float sW[8][260];
        #pragma unroll
        for (int it = 0; it < 2; it++) {
            int nt = (bx - 64) * 2 + it;
            if (it) __syncthreads();
            int row = tid >> 5;
            int kk = (tid & 31) * 8;
            const float* wr = W + (nt * 8 + row) * 256 + kk;
            #pragma unroll
            for (int u = 0; u < 8; u++) sW[row][kk + u] = wr[u];
            __syncthreads();
            #pragma unroll
            for (int t = 0; t < 4; t++) {
                int idx = t * 256 + tid;
                int ks = idx >> 5, lane = idx & 31;
                int g = lane >> 2, tg = lane & 3;
                float b0 = sW[g][ks * 8 + tg], b1 = sW[g][ks * 8 + 4 + tg];
                float h0, l0, h1, l1;
                split_tf32(b0, h0, l0);
                split_tf32(b1, h1, l1);
                ((float4*)g_Bfrag)[(nt * NKS + ks) * 32 + lane] = make_float4(h0, h1, l0, l1);
            }
        }
    } else {
        // ---- pair setup + counter resets (graph-replay safe) ----
        __shared__ int l1[BB];
        __shared__ int cnt[256];
        __shared__ int off[257];
        __shared__ int cj[BB];
        if (tid == 0) g_hc = 0;
        if (tid < BB) { g_hb[tid] = 0; l1[tid] = labels1[tid]; cj[tid] = 0; }
        __syncthreads();
        int base = tid * 16;
        int c = 0;
        #pragma unroll
        for (int u = 0; u < 16; u++) {
            int idx = base + u;
            c += (l1[idx >> 6] == l1[idx & 63]);
        }
        cnt[tid] = c;
        __syncthreads();
        if (tid == 0) {
            int acc = 0;
            for (int t = 0; t < 256; t++) { off[t] = acc; acc += cnt[t]; }
            off[256] = acc;
        }
        __syncthreads();
        int pos = off[tid];
        #pragma unroll
        for (int u = 0; u < 16; u++) {
            int idx = base + u;
            if (l1[idx >> 6] == l1[idx & 63]) {
                if (pos < PP) g_sel[pos] = idx;
                pos++;
            }
        }
        int total = off[256];
        for (int p2 = total + tid; p2 < PP; p2 += 256) g_sel[p2] = 0;
        __syncthreads();
        int nv = total < PP ? total : PP;
        for (int p = tid; p < PP; p += 256) {
            int s0 = g_sel[p];
            int i = s0 >> 6, j = s0 & 63;
            g_i[p] = i; g_j[p] = j;
            g_valid[p] = (p < nv) ? 1.0f : 0.0f;
            atomicAdd(&cj[j], 1);
        }
        __syncthreads();
        if (tid < BB) g_cj[tid] = (float)cj[tid];
    }
}

// ---------------- 2) QKV GEMM: one-wave fragment-direct tf32x3 -------------
// 128 blocks (16x8), block tile 128(M) x 96(N); warp tile 32x48; no smem.
__global__ void __launch_bounds__(256, 1) qkv_mma(const float* __restrict__ bias) {
    int bx = blockIdx.x;   // 0..15 (M)
    int by = blockIdx.y;   // 0..7  (N)
    int tid = threadIdx.x, warp = tid >> 5, lane = tid & 31;
    int g = lane >> 2, tg = lane & 3;
    int wr = warp >> 1, wc = warp & 1;
    int mtb = bx * 8 + wr * 2;     // 2 m-tiles per warp
    int ntb = by * 12 + wc * 6;    // 6 n-tiles per warp
    float c[2][6][4] = {};
    const float4* Af = (const float4*)g_Afrag;
    const float4* Bf = (const float4*)g_Bfrag;
    #pragma unroll 2
    for (int ks = 0; ks < NKS; ks++) {
        float4 ah[2], al[2], bf[6];
        #pragma unroll
        for (int mi = 0; mi < 2; mi++) {
            int ia = (((mtb + mi) * NKS + ks) * 32 + lane) * 2;
            ah[mi] = Af[ia];
            al[mi] = Af[ia + 1];
        }
        #pragma unroll
        for (int ni = 0; ni < 6; ni++)
            bf[ni] = Bf[((ntb + ni) * NKS + ks) * 32 + lane];
        #pragma unroll
        for (int mi = 0; mi < 2; mi++)
            #pragma unroll
            for (int ni = 0; ni < 6; ni++) {
                mma_tf32(c[mi][ni], ah[mi].x, ah[mi].y, ah[mi].z, ah[mi].w, bf[ni].x, bf[ni].y);
                mma_tf32(c[mi][ni], ah[mi].x, ah[mi].y, ah[mi].z, ah[mi].w, bf[ni].z, bf[ni].w);
                mma_tf32(c[mi][ni], al[mi].x, al[mi].y, al[mi].z, al[mi].w, bf[ni].x, bf[ni].y);
            }
    }
    #pragma unroll
    for (int mi = 0; mi < 2; mi++) {
        int m = bx * 128 + wr * 32 + mi * 16 + g;
        #pragma unroll
        for (int ni = 0; ni < 6; ni++) {
            int n = by * 96 + wc * 48 + ni * 8 + 2 * tg;
            float b0 = bias[n], b1 = bias[n + 1];
            *(float2*)(g_QKV + m * NCOLS + n) = make_float2(c[mi][ni][0] + b0, c[mi][ni][1] + b1);
            *(float2*)(g_QKV + (m + 8) * NCOLS + n) = make_float2(c[mi][ni][2] + b0, c[mi][ni][3] + b1);
        }
    }
}

// ---------------- 3) attention per (s,h): split-j, 1-pass softmax ----------
// (R12-proven form) 128 threads: half 0 does j in [0,32), half 1 j in [32,64).
__global__ void __launch_bounds__(128) attn_kernel() {
    int s = blockIdx.x & 31;
    int h = blockIdx.x >> 5;
    __shared__ float Ks[BB][HD];
    __shared__ float Vs[BB][HD];
    __shared__ float cjs[BB];
    __shared__ float Pd[BB];            // upper-half partial denom
    __shared__ float Pa[BB][HD + 1];    // upper-half partial acc (17: conflict-free)
    int tid = threadIdx.x;
    int half = tid >> 6;
    int b = tid & 63;

    const float* qkv_row = g_QKV + (b * SS + s) * NCOLS + h * HD;
    if (half == 0) {    // K rows + counts
        const float4* kp = (const float4*)(qkv_row + EE);
        float4* kd = (float4*)Ks[b];
        kd[0] = kp[0]; kd[1] = kp[1]; kd[2] = kp[2]; kd[3] = kp[3];
        cjs[b] = g_cj[b];
    } else {            // V rows
        const float4* vp = (const float4*)(qkv_row + 2 * EE);
        float4* vd = (float4*)Vs[b];
        vd[0] = vp[0]; vd[1] = vp[1]; vd[2] = vp[2]; vd[3] = vp[3];
    }
    float4 q0 = ((const float4*)qkv_row)[0];
    float4 q1 = ((const float4*)qkv_row)[1];
    float4 q2 = ((const float4*)qkv_row)[2];
    float4 q3 = ((const float4*)qkv_row)[3];
    __syncthreads();

    float denom = 0.0f;
    float acc[HD];
    #pragma unroll
    for (int d = 0; d < HD; d++) acc[d] = 0.0f;
    int j0 = half << 5;
    #pragma unroll 4
    for (int jj = 0; jj < 32; jj++) {
        int j = j0 + jj;
        const float4* kr = (const float4*)Ks[j];
        float4 k0 = kr[0], k1 = kr[1], k2 = kr[2], k3 = kr[3];
        float p0 = q0.x * k0.x + q0.y * k0.y + q0.z * k0.z + q0.w * k0.w;
        float p1 = q1.x * k1.x + q1.y * k1.y + q1.z * k1.z + q1.w * k1.w;
        float p2 = q2.x * k2.x + q2.y * k2.y + q2.z * k2.z + q2.w * k2.w;
        float p3 = q3.x * k3.x + q3.y * k3.y + q3.z * k3.z + q3.w * k3.w;
        float sc = ((p0 + p1) + (p2 + p3)) * 0.25f;
        float p = cjs[j] * __expf(sc);     // scores O(1): no max pass (validated R7+)
        denom += p;
        const float4* vr = (const float4*)Vs[j];
        float4 v0 = vr[0], v1 = vr[1], v2 = vr[2], v3 = vr[3];
        acc[0] += p * v0.x;  acc[1] += p * v0.y;  acc[2] += p * v0.z;  acc[3] += p * v0.w;
        acc[4] += p * v1.x;  acc[5] += p * v1.y;  acc[6] += p * v1.z;  acc[7] += p * v1.w;
        acc[8] += p * v2.x;  acc[9] += p * v2.y;  acc[10] += p * v2.z; acc[11] += p * v2.w;
        acc[12] += p * v3.x; acc[13] += p * v3.y; acc[14] += p * v3.z; acc[15] += p * v3.w;
    }
    if (half) {
        Pd[b] = denom;
        #pragma unroll
        for (int d = 0; d < HD; d++) Pa[b][d] = acc[d];
    }
    __syncthreads();
    if (!half) {
        denom += Pd[b];
        float inv = 1.0f / denom;
        float* op = g_O + (b * SS + s) * EE + h * HD;
        #pragma unroll
        for (int d = 0; d < HD; d++) op[d] = (acc[d] + Pa[b][d]) * inv;
    }
}

// ---------------- 4) head: 128 blocks (b, half-rows); 2nd arrival does -----
// logits+softmax for its b; global last block (128th) does the loss.
__global__ void __launch_bounds__(512) head_kernel(const float* __restrict__ Wo,
                                                   const float* __restrict__ bo,
                                                   const float* __restrict__ fw,
                                                   const float* __restrict__ fb,
                                                   const float* __restrict__ Hw,
                                                   const float* __restrict__ hb,
                                                   const int* __restrict__ labels0,
                                                   float* __restrict__ out) {
    int bx = blockIdx.x;
    int b = bx >> 1;
    int halfblk = bx & 1;
    __shared__ float Gs[EE];       // G, then reused as hs for the logits phase
    __shared__ float Gp[EE];
    __shared__ float hp[3][128];
    __shared__ float ls[64];
    __shared__ float lp[64];
    __shared__ float fws[SS];
    __shared__ float sfw_sh;
    __shared__ unsigned lastb_sh, last_sh;
    int tid = threadIdx.x;
    int half = tid >> 8;           // 0/1 (phase A s-split, logits k-split)
    int t = tid & 255;
    if (tid < SS) fws[tid] = fw[tid];
    __syncthreads();
    if (tid < 32) {
        float v = fws[tid];
        #pragma unroll
        for (int o = 16; o > 0; o >>= 1) v += __shfl_xor_sync(0xffffffffu, v, o);
        if (tid == 0) sfw_sh = v;
    }
    {   // phase A: G[e] — s-range split across halves, fixed-order combine
        const float* ob = g_O + b * SS * EE + t;
        int s0 = half * 16;
        float a0 = 0.0f, a1 = 0.0f;
        #pragma unroll
        for (int s = 0; s < 16; s += 2) {
            a0 += ob[(s0 + s) * EE] * fws[s0 + s];
            a1 += ob[(s0 + s + 1) * EE] * fws[s0 + s + 1];
        }
        if (half) Gp[t] = a0 + a1;
        __syncthreads();
        if (!half) Gs[t] = (a0 + a1) + Gp[t];
    }
    __syncthreads();
    {   // phase B: 128 h-rows for this (b, halfblk); 4-way k-split, 2 accums
        int rl = tid & 127;
        int q = tid >> 7;          // 0..3, 64-float k-segment each
        int r = halfblk * 128 + rl;
        const float4* wrow = (const float4*)(Wo + r * EE) + q * 16;
        const float4* gv4 = (const float4*)Gs + q * 16;
        float pa = 0.0f, pb = 0.0f;
        #pragma unroll 8
        for (int k = 0; k < 16; k += 2) {
            float4 wv = wrow[k];
            float4 gv = gv4[k];
            pa += wv.x * gv.x + wv.y * gv.y + wv.z * gv.z + wv.w * gv.w;
            float4 wv2 = wrow[k + 1];
            float4 gv2 = gv4[k + 1];
            pb += wv2.x * gv2.x + wv2.y * gv2.y + wv2.z * gv2.z + wv2.w * gv2.w;
        }
        float part = pa + pb;
        if (q) hp[q - 1][rl] = part;
        __syncthreads();
        if (q == 0)
            g_h[b * EE + r] = part + hp[0][rl] + hp[1][rl] + hp[2][rl]
                            + sfw_sh * bo[r] + fb[0];
    }
    // ---- per-b handoff: second-arriving block does logits/softmax ----
    __threadfence();
    __syncthreads();
    if (tid == 0) lastb_sh = (atomicAdd(&g_hb[b], 1u) == 1u);
    __syncthreads();
    if (lastb_sh) {                // uniform branch: internal syncs are safe
        __threadfence();
        if (tid < EE) Gs[tid] = g_h[b * EE + tid];   // reuse Gs as hs
        __syncthreads();
        {   // logits — k-split halves, store-and-combine
            float lpart = 0.0f;
            if (t < KC) {
                const float4* wrow = (const float4*)(Hw + t * EE) + half * 32;
                const float4* hv4 = (const float4*)Gs + half * 32;
                float pa = 0.0f, pb = 0.0f;
                #pragma unroll 8
                for (int k = 0; k < 32; k += 2) {
                    float4 wv = wrow[k];
                    float4 hv = hv4[k];
                    pa += wv.x * hv.x + wv.y * hv.y + wv.z * hv.z + wv.w * hv.w;
                    float4 wv2 = wrow[k + 1];
                    float4 hv2 = hv4[k + 1];
                    pb += wv2.x * hv2.x + wv2.y * hv2.y + wv2.z * hv2.z + wv2.w * hv2.w;
                }
                lpart = pa + pb;
                if (half) lp[t] = lpart;
            }
            __syncthreads();
            if (!half && t < KC) ls[t] = lpart + lp[t] + hb[t];
        }
        __syncthreads();
        if (tid < 32) {
            int lane = tid;
            float v1 = (lane < KC) ? ls[lane] : -1e30f;
            float v2 = (lane + 32 < KC) ? ls[lane + 32] : -1e30f;
            float mx = fmaxf(v1, v2);
            #pragma unroll
            for (int o = 16; o > 0; o >>= 1) mx = fmaxf(mx, __shfl_xor_sync(0xffffffffu, mx, o));
            float se = ((lane < KC) ? __expf(v1 - mx) : 0.0f)
                     + ((lane + 32 < KC) ? __expf(v2 - mx) : 0.0f);
            #pragma unroll
            for (int o = 16; o > 0; o >>= 1) se += __shfl_xor_sync(0xffffffffu, se, o);
            float lse = mx + logf(se);
            if (lane < KC) g_logprob[b * KC + lane] = v1 - lse;
            if (lane + 32 < KC) g_logprob[b * KC + lane + 32] = v2 - lse;
        }
    }
    // ---- global last-block loss (128th arrival ⇒ all logprob written) ----
    __threadfence();
    __syncthreads();
    if (tid == 0) last_sh = (atomicAdd(&g_hc, 1u) == 127u);
    __syncthreads();
    if (!last_sh) return;
    __threadfence();

    __shared__ int counts[KC];
    __shared__ float rn[16], rd[16];
    if (tid < KC) counts[tid] = 0;
    __syncthreads();
    // one pair per thread (512 threads = PP)
    int i = g_i[tid], j = g_j[tid];
    float valid = g_valid[tid];
    int a = labels0[i], c = labels0[j];
    int y;
    if (a == c) y = 0;
    else {
        int lo = min(a, c), hi = max(a, c);
        y = 1 + lo * 9 - (lo * (lo - 1)) / 2 + (hi - lo - 1);
    }
    if (valid > 0.0f) atomicAdd(&counts[y], 1);
    __syncthreads();
    float cw = counts[y] > 0 ? 1.0f / (float)counts[y] : 0.0f;
    float wy = cw * valid;
    float num = wy * (-g_logprob[i * KC + y]);
    float den = wy;
    int lane3 = tid & 31, w3 = tid >> 5;
    #pragma unroll
    for (int o = 16; o > 0; o >>= 1) {
        num += __shfl_down_sync(0xffffffffu, num, o);
        den += __shfl_down_sync(0xffffffffu, den, o);
    }
    if (lane3 == 0) { rn[w3] = num; rd[w3] = den; }
    __syncthreads();
    if (tid == 0) {
        float n2 = 0.0f, d2 = 0.0f;
        #pragma unroll
        for (int t2 = 0; t2 < 16; t2++) { n2 += rn[t2]; d2 += rd[t2]; }
        out[0] = n2 / d2;
    }
}

// ---------------------------------------------------------------------------
extern "C" void kernel_launch(void* const* d_in, const int* in_sizes, int n_in,
                              void* d_out, int out_size) {
    const float* feat    = (const float*)d_in[0];
    const int*   labels0 = (const int*)d_in[1];
    const int*   labels1 = (const int*)d_in[2];
    const float* ipw     = (const float*)d_in[3];
    const float* ipb     = (const float*)d_in[4];
    const float* opw     = (const float*)d_in[5];
    const float* opb     = (const float*)d_in[6];
    const float* fw      = (const float*)d_in[7];
    const float* fbv     = (const float*)d_in[8];
    const float* hw      = (const float*)d_in[9];
    const float* hbv     = (const float*)d_in[10];
    float* out = (float*)d_out;

    setup_kernel<<<113, 256>>>(feat, ipw, labels1);   // one wave
    dim3 g(16, 8);                            // one wave: 128 blocks
    qkv_mma<<<g, 256>>>(ipb);
    attn_kernel<<<SS * HH, 128>>>();          // 512 blocks, 2-way split-j (R12)
    head_kernel<<<BB * 2, 512>>>(opw, opb, fw, fbv, hw, hbv, labels0, out);
}